// round 5
// baseline (speedup 1.0000x reference)
#include <cuda_runtime.h>
#include <math.h>

#define BATCH 2
#define SEQ   4096
#define EMB   512
#define DQ    64
#define NC    129          // number of window diagonals
#define ZCONST 3967.0f     // 4096 - 129 zero-columns contributing exp(0)=1

// ---- scratch (allocation-free: device globals) ----
__device__ float g_Q[BATCH * SEQ * DQ];        // 2 MB
__device__ float g_K[BATCH * SEQ * DQ];        // 2 MB
__device__ float g_Vc[BATCH * NC * DQ];        // V rows 0..128
__device__ float g_part[BATCH * 64 * EMB];     // xsum partials (64 chunks)
__device__ float g_vtp[BATCH * 8 * DQ];        // vtail partials per k-group

// packed fp32x2 FMA (Blackwell FFMA2): acc = a*b + acc elementwise on 2 floats
__device__ __forceinline__ void ffma2(unsigned long long& acc,
                                      unsigned long long a,
                                      unsigned long long b) {
    asm("fma.rn.f32x2 %0, %1, %2, %0;" : "+l"(acc) : "l"(a), "l"(b));
}

// ============================================================
// Kernel 1: Q and K projections, FFMA2 k-pair formulation.
// ============================================================
#define XS_PITCH 130
#define PQ_XS  0
#define PQ_WQ  (64 * XS_PITCH)
#define PQ_WK  (2 * 64 * XS_PITCH)
#define PQ_FLOATS (3 * 64 * XS_PITCH)
#define PQ_BYTES (PQ_FLOATS * 4)

__global__ void __launch_bounds__(256, 1)
proj_qk_kernel(const float* __restrict__ x,
               const float* __restrict__ Wq, const float* __restrict__ bq,
               const float* __restrict__ Wk, const float* __restrict__ bk) {
    extern __shared__ float sm[];
    float* xs  = sm + PQ_XS;
    float* wqs = sm + PQ_WQ;
    float* wks = sm + PQ_WK;

    const int b  = blockIdx.y;
    const int n0 = blockIdx.x * 64;
    const int t  = threadIdx.x;
    const int d  = t & 63;
    const int rg = t >> 6;

    unsigned long long qa[16], ka[16];
#pragma unroll
    for (int i = 0; i < 16; i++) { qa[i] = 0ull; ka[i] = 0ull; }

    const float* xb = x + ((size_t)b * SEQ + n0) * EMB;

    for (int k0 = 0; k0 < EMB; k0 += 128) {
        __syncthreads();
        for (int idx = t; idx < 64 * 32; idx += 256) {
            int r = idx >> 5, c4 = idx & 31;
            float4 v = *(const float4*)(xb + (size_t)r * EMB + k0 + c4 * 4);
            float* p = xs + r * XS_PITCH + c4 * 4;
            p[0] = v.x; p[1] = v.y; p[2] = v.z; p[3] = v.w;
        }
        for (int idx = t; idx < 128 * 16; idx += 256) {
            int kk = idx >> 4, c4 = idx & 15;
            float4 q4 = *(const float4*)(Wq + (size_t)(k0 + kk) * DQ + c4 * 4);
            float4 k4 = *(const float4*)(Wk + (size_t)(k0 + kk) * DQ + c4 * 4);
            wqs[(c4 * 4 + 0) * XS_PITCH + kk] = q4.x;
            wqs[(c4 * 4 + 1) * XS_PITCH + kk] = q4.y;
            wqs[(c4 * 4 + 2) * XS_PITCH + kk] = q4.z;
            wqs[(c4 * 4 + 3) * XS_PITCH + kk] = q4.w;
            wks[(c4 * 4 + 0) * XS_PITCH + kk] = k4.x;
            wks[(c4 * 4 + 1) * XS_PITCH + kk] = k4.y;
            wks[(c4 * 4 + 2) * XS_PITCH + kk] = k4.z;
            wks[(c4 * 4 + 3) * XS_PITCH + kk] = k4.w;
        }
        __syncthreads();

        const unsigned long long* wq2 = (const unsigned long long*)(wqs + d * XS_PITCH);
        const unsigned long long* wk2 = (const unsigned long long*)(wks + d * XS_PITCH);
        const float* xrow0 = xs + (rg * 16) * XS_PITCH;

#pragma unroll 4
        for (int kp = 0; kp < 64; kp++) {
            unsigned long long w2q = wq2[kp];
            unsigned long long w2k = wk2[kp];
#pragma unroll
            for (int i = 0; i < 16; i++) {
                unsigned long long x2 =
                    *(const unsigned long long*)(xrow0 + i * XS_PITCH + kp * 2);
                ffma2(qa[i], x2, w2q);
                ffma2(ka[i], x2, w2k);
            }
        }
    }

    float bqv = bq[d], bkv = bk[d];
#pragma unroll
    for (int i = 0; i < 16; i++) {
        int n = n0 + rg * 16 + i;
        float qlo = __uint_as_float((unsigned)qa[i]);
        float qhi = __uint_as_float((unsigned)(qa[i] >> 32));
        float klo = __uint_as_float((unsigned)ka[i]);
        float khi = __uint_as_float((unsigned)(ka[i] >> 32));
        g_Q[((size_t)b * SEQ + n) * DQ + d] = qlo + qhi + bqv;
        g_K[((size_t)b * SEQ + n) * DQ + d] = klo + khi + bkv;
    }
}

// ============================================================
// Kernel 2: V projection, rows 0..128 only. 128 threads, split-k.
// ============================================================
__global__ void proj_vhead_kernel(const float* __restrict__ x,
                                  const float* __restrict__ Wv,
                                  const float* __restrict__ bv) {
    const int b = blockIdx.y, r = blockIdx.x, t = threadIdx.x;  // 128 threads
    __shared__ float xsh[EMB];
    __shared__ float red[2][DQ];
    const float* xr = x + ((size_t)b * SEQ + r) * EMB;
    ((float4*)xsh)[t] = ((const float4*)xr)[t];
    __syncthreads();
    const int d = t & 63, h = t >> 6;
    float acc = 0.f;
    const int kb = h * 256;
#pragma unroll 8
    for (int k = 0; k < 256; k++)
        acc = fmaf(xsh[kb + k], Wv[(size_t)(kb + k) * DQ + d], acc);
    red[h][d] = acc;
    __syncthreads();
    if (t < DQ)
        g_Vc[(b * NC + r) * DQ + t] = red[0][t] + red[1][t] + bv[t];
}

// ============================================================
// Kernel 3: partial row-sums of x over rows 129..4095. 64 chunks x 2b.
// ============================================================
__global__ void xsum_partial_kernel(const float* __restrict__ x) {
    const int b = blockIdx.y, ci = blockIdx.x, t = threadIdx.x;  // 128 threads
    int r0 = 129 + ci * 62;
    int r1 = r0 + 62; if (r1 > SEQ) r1 = SEQ;
    const float* xb = x + (size_t)b * SEQ * EMB;
    float4 s = make_float4(0.f, 0.f, 0.f, 0.f);
#pragma unroll 4
    for (int r = r0; r < r1; r++) {
        float4 v = *(const float4*)(xb + (size_t)r * EMB + t * 4);
        s.x += v.x; s.y += v.y; s.z += v.z; s.w += v.w;
    }
    *(float4*)(g_part + (b * 64 + ci) * EMB + t * 4) = s;
}

// ============================================================
// Kernel 4: vtail partial per k-group: grid (8, 2), 256 threads.
//  g_vtp[b][kg][d] = (sum_ci g_part[b][ci][kg*64..]) . Wv[kg*64.., d]
// ============================================================
__global__ void vtail_combine_kernel(const float* __restrict__ Wv) {
    const int kg = blockIdx.x, b = blockIdx.y, t = threadIdx.x;
    __shared__ float red[4][DQ];
    __shared__ float xsum64[DQ];
    __shared__ float p2[4][DQ];
    {
        const int kk = t & 63, g = t >> 6;
        float s = 0.f;
#pragma unroll
        for (int ci = g; ci < 64; ci += 4)
            s += g_part[(b * 64 + ci) * EMB + kg * 64 + kk];
        red[g][kk] = s;
    }
    __syncthreads();
    if (t < DQ) xsum64[t] = red[0][t] + red[1][t] + red[2][t] + red[3][t];
    __syncthreads();
    {
        const int d = t & 63, g2 = t >> 6;
        float acc = 0.f;
#pragma unroll
        for (int kk = g2 * 16; kk < g2 * 16 + 16; kk++)
            acc = fmaf(xsum64[kk], Wv[(size_t)(kg * 64 + kk) * DQ + d], acc);
        p2[g2][d] = acc;
    }
    __syncthreads();
    if (t < DQ)
        g_vtp[(b * 8 + kg) * DQ + t] = p2[0][t] + p2[1][t] + p2[2][t] + p2[3][t];
}

// ============================================================
// Kernel 5: attention core, FFMA2 in both GEMM phases.
// ============================================================
#define KS_PITCH 66     // even -> 8B-aligned pairs; 33 mod 16 = 1 -> conflict-free
#define ES_PITCH 130    // even; 65 mod 16 = 1 -> conflict-free
#define SM_KS  0
#define SM_QS  (192 * KS_PITCH)                  // 12672
#define SM_ES  (SM_QS + 64 * KS_PITCH)           // 16896
#define SM_VST (SM_ES + 64 * ES_PITCH)           // 25216
#define SM_ZI  (SM_VST + 64 * ES_PITCH)          // 33536
#define SM_VT  (SM_ZI + 64)
#define SM_FLOATS (SM_VT + 64)
#define SM_BYTES (SM_FLOATS * 4)

__global__ void __launch_bounds__(256, 1)
attn_kernel(float* __restrict__ out, const float* __restrict__ bv) {
    extern __shared__ float sm[];
    float* Ks  = sm + SM_KS;
    float* Qs  = sm + SM_QS;
    float* Es  = sm + SM_ES;
    float* Vst = sm + SM_VST;    // transposed V: Vst[d][c], c contiguous
    float* Zi  = sm + SM_ZI;
    float* Vt  = sm + SM_VT;

    const int b = blockIdx.y, n0 = blockIdx.x * 64, t = threadIdx.x;

    // --- stage K window (192 rows, zero-padded) ---
    const float* Kb = g_K + (size_t)b * SEQ * DQ;
    for (int idx = t; idx < 192 * 16; idx += 256) {
        int r = idx >> 4, c4 = idx & 15;
        int j = n0 - 64 + r;
        float4 v = (j >= 0 && j < SEQ) ? *(const float4*)(Kb + (size_t)j * DQ + c4 * 4)
                                       : make_float4(0.f, 0.f, 0.f, 0.f);
        float* p = Ks + r * KS_PITCH + c4 * 4;
        p[0] = v.x; p[1] = v.y; p[2] = v.z; p[3] = v.w;
    }
    // --- stage Q tile ---
    const float* Qb = g_Q + ((size_t)b * SEQ + n0) * DQ;
    for (int idx = t; idx < 64 * 16; idx += 256) {
        int r = idx >> 4, c4 = idx & 15;
        float4 v = *(const float4*)(Qb + (size_t)r * DQ + c4 * 4);
        float* p = Qs + r * KS_PITCH + c4 * 4;
        p[0] = v.x; p[1] = v.y; p[2] = v.z; p[3] = v.w;
    }
    // --- stage V transposed: Vst[d][c] = Vc[c][d]; pad c=129 with 0 ---
    for (int idx = t; idx < NC * 16; idx += 256) {
        int r = idx >> 4, c4 = idx & 15;     // r = c index, c4*4.. = d
        float4 v = *(const float4*)(g_Vc + ((size_t)b * NC + r) * DQ + c4 * 4);
        Vst[(c4 * 4 + 0) * ES_PITCH + r] = v.x;
        Vst[(c4 * 4 + 1) * ES_PITCH + r] = v.y;
        Vst[(c4 * 4 + 2) * ES_PITCH + r] = v.z;
        Vst[(c4 * 4 + 3) * ES_PITCH + r] = v.w;
    }
    if (t < DQ) {
        Vst[t * ES_PITCH + 129] = 0.f;
        Es[t * ES_PITCH + 129]  = 0.f;
        float s = ZCONST * bv[t];
#pragma unroll
        for (int kg = 0; kg < 8; kg++) s += g_vtp[(b * 8 + kg) * DQ + t];
        Vt[t] = s;
    }
    __syncthreads();

    const int tx = t & 15, ty = t >> 4;

    // --- phase 1: S(64x192) = Q * Ks^T, FFMA2 over k-pairs ---
    unsigned long long acc2[4][12];
#pragma unroll
    for (int i = 0; i < 4; i++)
#pragma unroll
        for (int jj = 0; jj < 12; jj++) acc2[i][jj] = 0ull;

#pragma unroll 4
    for (int kp = 0; kp < 32; kp++) {
        unsigned long long qv[4], kv[12];
#pragma unroll
        for (int i = 0; i < 4; i++)
            qv[i] = *(const unsigned long long*)(Qs + (ty * 4 + i) * KS_PITCH + kp * 2);
#pragma unroll
        for (int jj = 0; jj < 12; jj++)
            kv[jj] = *(const unsigned long long*)(Ks + (tx + 16 * jj) * KS_PITCH + kp * 2);
#pragma unroll
        for (int i = 0; i < 4; i++)
#pragma unroll
            for (int jj = 0; jj < 12; jj++)
                ffma2(acc2[i][jj], qv[i], kv[jj]);
    }

    // --- phase 1.5: exp + scatter into Es[row][c], c = cc - n' ---
#pragma unroll
    for (int i = 0; i < 4; i++) {
        int np = ty * 4 + i;
#pragma unroll
        for (int jj = 0; jj < 12; jj++) {
            int cc = tx + 16 * jj;
            int c = cc - np;
            if (c >= 0 && c < NC) {
                float lo = __uint_as_float((unsigned)acc2[i][jj]);
                float hi = __uint_as_float((unsigned)(acc2[i][jj] >> 32));
                Es[np * ES_PITCH + c] = expf(lo + hi);
            }
        }
    }
    __syncthreads();

    // --- Z per row ---
    {
        const int w = t >> 5, lane = t & 31;
        for (int rr = 0; rr < 8; rr++) {
            int r = w * 8 + rr;
            float s = Es[r * ES_PITCH + lane] + Es[r * ES_PITCH + lane + 32]
                    + Es[r * ES_PITCH + lane + 64] + Es[r * ES_PITCH + lane + 96];
            if (lane == 0) s += Es[r * ES_PITCH + 128];
#pragma unroll
            for (int o = 16; o > 0; o >>= 1) s += __shfl_xor_sync(0xffffffffu, s, o);
            if (lane == 0) Zi[r] = 1.0f / (s + ZCONST);
        }
    }
    __syncthreads();

    // --- phase 2: O = E(64x130) * V^T, FFMA2 over c-pairs (65 pairs) ---
    unsigned long long oacc2[4][4];
#pragma unroll
    for (int i = 0; i < 4; i++)
#pragma unroll
        for (int i2 = 0; i2 < 4; i2++) oacc2[i][i2] = 0ull;

#pragma unroll 5
    for (int kp = 0; kp < 65; kp++) {
        unsigned long long ev[4], vv[4];
#pragma unroll
        for (int i = 0; i < 4; i++)
            ev[i] = *(const unsigned long long*)(Es + (ty * 4 + i) * ES_PITCH + kp * 2);
#pragma unroll
        for (int i2 = 0; i2 < 4; i2++)
            vv[i2] = *(const unsigned long long*)(Vst + (tx + 16 * i2) * ES_PITCH + kp * 2);
#pragma unroll
        for (int i = 0; i < 4; i++)
#pragma unroll
            for (int i2 = 0; i2 < 4; i2++)
                ffma2(oacc2[i][i2], ev[i], vv[i2]);
    }

#pragma unroll
    for (int i = 0; i < 4; i++) {
        int np = ty * 4 + i;
        float zi = Zi[np];
#pragma unroll
        for (int i2 = 0; i2 < 4; i2++) {
            int d = tx + 16 * i2;
            float lo = __uint_as_float((unsigned)oacc2[i][i2]);
            float hi = __uint_as_float((unsigned)(oacc2[i][i2] >> 32));
            out[((size_t)b * SEQ + n0 + np) * DQ + d] = (lo + hi + Vt[d]) * zi;
        }
    }
}

// ============================================================
// launcher
// ============================================================
extern "C" void kernel_launch(void* const* d_in, const int* in_sizes, int n_in,
                              void* d_out, int out_size) {
    const float* x  = (const float*)d_in[0];
    const float* Wq = (const float*)d_in[1];
    const float* bq = (const float*)d_in[2];
    const float* Wk = (const float*)d_in[3];
    const float* bk = (const float*)d_in[4];
    const float* Wv = (const float*)d_in[5];
    const float* bv = (const float*)d_in[6];
    float* out = (float*)d_out;

    cudaFuncSetAttribute(proj_qk_kernel, cudaFuncAttributeMaxDynamicSharedMemorySize, PQ_BYTES);
    cudaFuncSetAttribute(attn_kernel,    cudaFuncAttributeMaxDynamicSharedMemorySize, SM_BYTES);

    xsum_partial_kernel<<<dim3(64, BATCH), 128>>>(x);
    proj_vhead_kernel<<<dim3(NC, BATCH), 128>>>(x, Wv, bv);
    vtail_combine_kernel<<<dim3(8, BATCH), 256>>>(Wv);
    proj_qk_kernel<<<dim3(SEQ / 64, BATCH), 256, PQ_BYTES>>>(x, Wq, bq, Wk, bk);
    attn_kernel<<<dim3(SEQ / 64, BATCH), 256, SM_BYTES>>>(out, bv);
}